// round 6
// baseline (speedup 1.0000x reference)
#include <cuda_runtime.h>

#define N_CELLS 50000
#define N_EDGES 1600000
#define D_IN 256
#define D_OUT 128

// ---- scratch (device globals; no allocation allowed) ----
__device__ float g_m[N_CELLS * D_OUT];      // x @ W  (sequential-k fma chain, cublas-like)
__device__ float g_ssrc[N_CELLS];           // warp-gemv order dots
__device__ float g_sdst[N_CELLS];
__device__ int   g_cnt[N_CELLS];
__device__ int   g_ptr[N_CELLS];            // excl prefix, then fill cursor / row ends
__device__ int2  g_pairs[N_EDGES];          // (dst, float_bits(n_val)) grouped by src

// ================= GEMM: g_m = x @ W (sequential k-ascending fma per element) =================
#define BM 128
#define BN 128
#define BK 16

__global__ __launch_bounds__(256) void gemm_kernel(const float* __restrict__ x,
                                                   const float* __restrict__ W) {
    __shared__ float As[BK][BM + 1];
    __shared__ float Bs[BK][BN];
    const int tid = threadIdx.x;
    const int blockRow = blockIdx.x * BM;
    const int tx = tid & 15;
    const int ty = tid >> 4;

    float acc[8][8];
#pragma unroll
    for (int r = 0; r < 8; r++)
#pragma unroll
        for (int c = 0; c < 8; c++) acc[r][c] = 0.f;

    const int rowA = tid >> 2;
    const int colA = (tid & 3) << 2;
    const int rowB = tid >> 5;
    const int colB = (tid & 31) << 2;

    for (int kk = 0; kk < D_IN; kk += BK) {
#pragma unroll
        for (int h = 0; h < 2; h++) {
            int r = rowA + h * 64;
            int gr = blockRow + r;
            float4 v = make_float4(0.f, 0.f, 0.f, 0.f);
            if (gr < N_CELLS)
                v = *(const float4*)(x + (size_t)gr * D_IN + kk + colA);
            As[colA + 0][r] = v.x;
            As[colA + 1][r] = v.y;
            As[colA + 2][r] = v.z;
            As[colA + 3][r] = v.w;
        }
#pragma unroll
        for (int h = 0; h < 2; h++) {
            int r = rowB + h * 8;
            float4 v = *(const float4*)(W + (size_t)(kk + r) * D_OUT + colB);
            *(float4*)(&Bs[r][colB]) = v;
        }
        __syncthreads();
#pragma unroll
        for (int k = 0; k < BK; k++) {
            float regM[8], regN[8];
#pragma unroll
            for (int r = 0; r < 8; r++) regM[r] = As[k][ty * 8 + r];
#pragma unroll
            for (int c = 0; c < 8; c++) regN[c] = Bs[k][tx * 8 + c];
#pragma unroll
            for (int r = 0; r < 8; r++)
#pragma unroll
                for (int c = 0; c < 8; c++)
                    acc[r][c] = fmaf(regM[r], regN[c], acc[r][c]);
        }
        __syncthreads();
    }
#pragma unroll
    for (int r = 0; r < 8; r++) {
        int gr = blockRow + ty * 8 + r;
        if (gr < N_CELLS) {
            float* dst = g_m + (size_t)gr * D_OUT + tx * 8;
            *(float4*)dst = make_float4(acc[r][0], acc[r][1], acc[r][2], acc[r][3]);
            *(float4*)(dst + 4) = make_float4(acc[r][4], acc[r][5], acc[r][6], acc[r][7]);
        }
    }
}

// ================= scores: cublas-gemv emulation =================
// warp per row; lane l: fma chain over k = l, l+32, l+64, l+96 (ascending),
// then shfl-down tree (16,8,4,2,1); lane 0 holds the result.
__global__ __launch_bounds__(256) void score_kernel(const float* __restrict__ a) {
    __shared__ float sa[2 * D_OUT];
    for (int j = threadIdx.x; j < 2 * D_OUT; j += blockDim.x) sa[j] = a[j];
    __syncthreads();
    int row = (blockIdx.x * blockDim.x + threadIdx.x) >> 5;
    int l = threadIdx.x & 31;
    if (row >= N_CELLS) return;
    const float* __restrict__ mr = g_m + (size_t)row * D_OUT;

    float m0 = __ldg(mr + l);
    float m1 = __ldg(mr + l + 32);
    float m2 = __ldg(mr + l + 64);
    float m3 = __ldg(mr + l + 96);

    float ss = fmaf(m0, sa[l], 0.f);
    ss = fmaf(m1, sa[l + 32], ss);
    ss = fmaf(m2, sa[l + 64], ss);
    ss = fmaf(m3, sa[l + 96], ss);

    float sd = fmaf(m0, sa[D_OUT + l], 0.f);
    sd = fmaf(m1, sa[D_OUT + l + 32], sd);
    sd = fmaf(m2, sa[D_OUT + l + 64], sd);
    sd = fmaf(m3, sa[D_OUT + l + 96], sd);

#pragma unroll
    for (int off = 16; off > 0; off >>= 1) {
        ss += __shfl_down_sync(0xffffffffu, ss, off);
        sd += __shfl_down_sync(0xffffffffu, sd, off);
    }
    if (l == 0) {
        g_ssrc[row] = ss;
        g_sdst[row] = sd;
    }
}

// ================= CSR build =================
__global__ void zero_kernel() {
    int i = blockIdx.x * blockDim.x + threadIdx.x;
    if (i < N_CELLS) g_cnt[i] = 0;
}

__global__ void hist_kernel(const int* __restrict__ n_src) {
    int e = blockIdx.x * blockDim.x + threadIdx.x;
    if (e < N_EDGES) atomicAdd(&g_cnt[n_src[e]], 1);
}

__global__ __launch_bounds__(1024) void scan_kernel() {
    __shared__ int sw[32];
    __shared__ int s_carry;
    const int tid = threadIdx.x, lane = tid & 31, wid = tid >> 5;
    if (tid == 0) s_carry = 0;
    __syncthreads();
    for (int base = 0; base < N_CELLS; base += 1024) {
        int i = base + tid;
        int v = (i < N_CELLS) ? g_cnt[i] : 0;
        int xv = v;
#pragma unroll
        for (int off = 1; off < 32; off <<= 1) {
            int y = __shfl_up_sync(0xffffffffu, xv, off);
            if (lane >= off) xv += y;
        }
        if (lane == 31) sw[wid] = xv;
        __syncthreads();
        if (wid == 0) {
            int s = sw[lane];
#pragma unroll
            for (int off = 1; off < 32; off <<= 1) {
                int y = __shfl_up_sync(0xffffffffu, s, off);
                if (lane >= off) s += y;
            }
            sw[lane] = s;
        }
        __syncthreads();
        int offset = s_carry + (wid > 0 ? sw[wid - 1] : 0);
        if (i < N_CELLS) g_ptr[i] = offset + xv - v;
        __syncthreads();
        if (tid == 0) s_carry += sw[31];
        __syncthreads();
    }
}

__global__ void scatter_kernel(const int* __restrict__ n_src,
                               const int* __restrict__ n_dst,
                               const float* __restrict__ n_vals) {
    int e = blockIdx.x * blockDim.x + threadIdx.x;
    if (e < N_EDGES) {
        int pos = atomicAdd(&g_ptr[n_src[e]], 1);
        g_pairs[pos] = make_int2(n_dst[e], __float_as_int(n_vals[e]));
    }
}

// ================= aggregation: one warp per cell =================
// rs accumulated in fp64 (exact; best estimator of ref's randomly-ordered
// fp32 atomic fold). Numerator in fp32.
__global__ __launch_bounds__(256) void agg_kernel(float* __restrict__ out) {
    int i = (blockIdx.x * blockDim.x + threadIdx.x) >> 5;
    int lane = threadIdx.x & 31;
    if (i >= N_CELLS) return;
    int start = (i > 0) ? g_ptr[i - 1] : 0;
    int end = g_ptr[i];
    float si = g_ssrc[i];

    // pass 1: rs (fp64, lane-parallel then exact-enough warp reduce)
    double rsd = 0.0;
    for (int j = start + lane; j < end; j += 32) {
        int dst = g_pairs[j].x;
        float z = si + g_sdst[dst];
        float e = z >= 0.f ? z : 0.2f * z;
        rsd += (double)e;
    }
#pragma unroll
    for (int off = 16; off > 0; off >>= 1)
        rsd += __shfl_xor_sync(0xffffffffu, rsd, off);
    float rsf = (float)rsd;

    // pass 2: numerator; all lanes iterate all edges, each owns 4 output cols
    float4 acc = make_float4(0.f, 0.f, 0.f, 0.f);
    const float4* __restrict__ M4 = (const float4*)g_m;
    for (int j = start; j < end; j++) {
        int2 p = g_pairs[j];
        float z = si + g_sdst[p.x];
        float e = z >= 0.f ? z : 0.2f * z;
        float att = e / rsf;
        float t = __int_as_float(p.y) * att;
        float4 mv = __ldg(&M4[(size_t)p.x * 32 + lane]);
        acc.x = fmaf(t, mv.x, acc.x);
        acc.y = fmaf(t, mv.y, acc.y);
        acc.z = fmaf(t, mv.z, acc.z);
        acc.w = fmaf(t, mv.w, acc.w);
    }
    *((float4*)(out + (size_t)i * D_OUT) + lane) = acc;
}

// ================= launch =================
extern "C" void kernel_launch(void* const* d_in, const int* in_sizes, int n_in,
                              void* d_out, int out_size) {
    const float* x      = (const float*)d_in[0];
    const float* W      = (const float*)d_in[1];
    const float* a      = (const float*)d_in[2];
    const float* n_vals = (const float*)d_in[3];
    const int*   n_src  = (const int*)d_in[4];
    const int*   n_dst  = (const int*)d_in[5];
    float* out = (float*)d_out;

    const int gemm_blocks = (N_CELLS + BM - 1) / BM;            // 391
    gemm_kernel<<<gemm_blocks, 256>>>(x, W);

    const int warp_blocks = (N_CELLS * 32 + 255) / 256;         // 6250
    score_kernel<<<warp_blocks, 256>>>(a);

    zero_kernel<<<(N_CELLS + 255) / 256, 256>>>();
    hist_kernel<<<(N_EDGES + 255) / 256, 256>>>(n_src);
    scan_kernel<<<1, 1024>>>();
    scatter_kernel<<<(N_EDGES + 255) / 256, 256>>>(n_src, n_dst, n_vals);

    agg_kernel<<<warp_blocks, 256>>>(out);
}

// round 7
// speedup vs baseline: 1.1209x; 1.1209x over previous
#include <cuda_runtime.h>

#define N_CELLS 50000
#define N_EDGES 1600000
#define D_IN 256
#define D_OUT 128
#define MAXD 128

// ---- scratch (device globals; no allocation allowed) ----
__device__ float g_m[N_CELLS * D_OUT];      // x @ W  (sequential-k fma chain, cublas-like)
__device__ float g_ssrc[N_CELLS];           // warp-gemv order dots
__device__ float g_sdst[N_CELLS];
__device__ int   g_cnt[N_CELLS];
__device__ int   g_rowstart[N_CELLS];       // contiguous (not monotonic) row ranges
__device__ int   g_fill[N_CELLS];           // scatter cursor
__device__ int   g_total;
__device__ int2  g_pairs[N_EDGES];          // (dst, float_bits(n_val)) grouped by src

// ================= GEMM: g_m = x @ W (sequential k-ascending fma per element) =================
#define BM 128
#define BN 128
#define BK 16

__global__ __launch_bounds__(256) void gemm_kernel(const float* __restrict__ x,
                                                   const float* __restrict__ W) {
    __shared__ float As[BK][BM + 1];
    __shared__ float Bs[BK][BN];
    const int tid = threadIdx.x;
    const int blockRow = blockIdx.x * BM;
    const int tx = tid & 15;
    const int ty = tid >> 4;

    float acc[8][8];
#pragma unroll
    for (int r = 0; r < 8; r++)
#pragma unroll
        for (int c = 0; c < 8; c++) acc[r][c] = 0.f;

    const int rowA = tid >> 2;
    const int colA = (tid & 3) << 2;
    const int rowB = tid >> 5;
    const int colB = (tid & 31) << 2;

    for (int kk = 0; kk < D_IN; kk += BK) {
#pragma unroll
        for (int h = 0; h < 2; h++) {
            int r = rowA + h * 64;
            int gr = blockRow + r;
            float4 v = make_float4(0.f, 0.f, 0.f, 0.f);
            if (gr < N_CELLS)
                v = *(const float4*)(x + (size_t)gr * D_IN + kk + colA);
            As[colA + 0][r] = v.x;
            As[colA + 1][r] = v.y;
            As[colA + 2][r] = v.z;
            As[colA + 3][r] = v.w;
        }
#pragma unroll
        for (int h = 0; h < 2; h++) {
            int r = rowB + h * 8;
            float4 v = *(const float4*)(W + (size_t)(kk + r) * D_OUT + colB);
            *(float4*)(&Bs[r][colB]) = v;
        }
        __syncthreads();
#pragma unroll
        for (int k = 0; k < BK; k++) {
            float regM[8], regN[8];
#pragma unroll
            for (int r = 0; r < 8; r++) regM[r] = As[k][ty * 8 + r];
#pragma unroll
            for (int c = 0; c < 8; c++) regN[c] = Bs[k][tx * 8 + c];
#pragma unroll
            for (int r = 0; r < 8; r++)
#pragma unroll
                for (int c = 0; c < 8; c++)
                    acc[r][c] = fmaf(regM[r], regN[c], acc[r][c]);
        }
        __syncthreads();
    }
#pragma unroll
    for (int r = 0; r < 8; r++) {
        int gr = blockRow + ty * 8 + r;
        if (gr < N_CELLS) {
            float* dst = g_m + (size_t)gr * D_OUT + tx * 8;
            *(float4*)dst = make_float4(acc[r][0], acc[r][1], acc[r][2], acc[r][3]);
            *(float4*)(dst + 4) = make_float4(acc[r][4], acc[r][5], acc[r][6], acc[r][7]);
        }
    }
}

// ================= scores: cublas-gemv emulation (FROZEN numerics) =================
__global__ __launch_bounds__(256) void score_kernel(const float* __restrict__ a) {
    __shared__ float sa[2 * D_OUT];
    for (int j = threadIdx.x; j < 2 * D_OUT; j += blockDim.x) sa[j] = a[j];
    __syncthreads();
    int row = (blockIdx.x * blockDim.x + threadIdx.x) >> 5;
    int l = threadIdx.x & 31;
    if (row >= N_CELLS) return;
    const float* __restrict__ mr = g_m + (size_t)row * D_OUT;

    float m0 = __ldg(mr + l);
    float m1 = __ldg(mr + l + 32);
    float m2 = __ldg(mr + l + 64);
    float m3 = __ldg(mr + l + 96);

    float ss = fmaf(m0, sa[l], 0.f);
    ss = fmaf(m1, sa[l + 32], ss);
    ss = fmaf(m2, sa[l + 64], ss);
    ss = fmaf(m3, sa[l + 96], ss);

    float sd = fmaf(m0, sa[D_OUT + l], 0.f);
    sd = fmaf(m1, sa[D_OUT + l + 32], sd);
    sd = fmaf(m2, sa[D_OUT + l + 64], sd);
    sd = fmaf(m3, sa[D_OUT + l + 96], sd);

#pragma unroll
    for (int off = 16; off > 0; off >>= 1) {
        ss += __shfl_down_sync(0xffffffffu, ss, off);
        sd += __shfl_down_sync(0xffffffffu, sd, off);
    }
    if (l == 0) {
        g_ssrc[row] = ss;
        g_sdst[row] = sd;
    }
}

// ================= CSR build (scan-free) =================
__global__ void zero_kernel() {
    int i = blockIdx.x * blockDim.x + threadIdx.x;
    if (i < N_CELLS) g_cnt[i] = 0;
    if (i == 0) g_total = 0;
}

__global__ void hist_kernel(const int* __restrict__ n_src) {
    int e = blockIdx.x * blockDim.x + threadIdx.x;
    if (e < N_EDGES) atomicAdd(&g_cnt[n_src[e]], 1);
}

// warp-aggregated range allocation: contiguous ranges, arbitrary order
__global__ __launch_bounds__(256) void alloc_kernel() {
    int i = blockIdx.x * blockDim.x + threadIdx.x;
    int lane = threadIdx.x & 31;
    int cnt = (i < N_CELLS) ? g_cnt[i] : 0;
    int xv = cnt;
#pragma unroll
    for (int off = 1; off < 32; off <<= 1) {
        int y = __shfl_up_sync(0xffffffffu, xv, off);
        if (lane >= off) xv += y;
    }
    int excl = xv - cnt;
    int wtotal = __shfl_sync(0xffffffffu, xv, 31);
    int base = 0;
    if (lane == 0) base = atomicAdd(&g_total, wtotal);
    base = __shfl_sync(0xffffffffu, base, 0);
    if (i < N_CELLS) {
        int s = base + excl;
        g_rowstart[i] = s;
        g_fill[i] = s;
    }
}

__global__ void scatter_kernel(const int* __restrict__ n_src,
                               const int* __restrict__ n_dst,
                               const float* __restrict__ n_vals) {
    int e = blockIdx.x * blockDim.x + threadIdx.x;
    if (e < N_EDGES) {
        int pos = atomicAdd(&g_fill[n_src[e]], 1);
        g_pairs[pos] = make_int2(n_dst[e], __float_as_int(n_vals[e]));
    }
}

// ================= aggregation: one warp per cell (FROZEN numerics) =================
__global__ __launch_bounds__(256) void agg_kernel(float* __restrict__ out) {
    __shared__ float ebuf[8][MAXD];
    const int w = threadIdx.x >> 5;
    int i = (blockIdx.x * blockDim.x + threadIdx.x) >> 5;
    int lane = threadIdx.x & 31;
    if (i >= N_CELLS) return;
    int start = g_rowstart[i];
    int d = g_cnt[i];
    int end = start + d;
    float si = g_ssrc[i];

    // pass 1: e values + fp64 rs
    double rsd = 0.0;
    for (int j = start + lane; j < end; j += 32) {
        int dst = g_pairs[j].x;
        float z = si + g_sdst[dst];
        float e = z >= 0.f ? z : 0.2f * z;
        int t = j - start;
        if (t < MAXD) ebuf[w][t] = e;
        rsd += (double)e;
    }
#pragma unroll
    for (int off = 16; off > 0; off >>= 1)
        rsd += __shfl_xor_sync(0xffffffffu, rsd, off);
    float rsf = (float)rsd;
    __syncwarp();

    // pass 2: numerator; lanes own 4 output cols each
    float4 acc = make_float4(0.f, 0.f, 0.f, 0.f);
    const float4* __restrict__ M4 = (const float4*)g_m;
#pragma unroll 2
    for (int t = 0; t < d; t++) {
        int2 p = g_pairs[start + t];
        float e;
        if (t < MAXD) {
            e = ebuf[w][t];
        } else {
            float z = si + g_sdst[p.x];
            e = z >= 0.f ? z : 0.2f * z;
        }
        float att = e / rsf;
        float tt = __int_as_float(p.y) * att;
        float4 mv = __ldg(&M4[(size_t)p.x * 32 + lane]);
        acc.x = fmaf(tt, mv.x, acc.x);
        acc.y = fmaf(tt, mv.y, acc.y);
        acc.z = fmaf(tt, mv.z, acc.z);
        acc.w = fmaf(tt, mv.w, acc.w);
    }
    *((float4*)(out + (size_t)i * D_OUT) + lane) = acc;
}

// ================= launch (fork/join: CSR build overlaps GEMM) =================
struct HbsRes {
    cudaStream_t s2;
    cudaEvent_t evFork, evJoin;
    HbsRes() {
        cudaStreamCreateWithFlags(&s2, cudaStreamNonBlocking);
        cudaEventCreateWithFlags(&evFork, cudaEventDisableTiming);
        cudaEventCreateWithFlags(&evJoin, cudaEventDisableTiming);
    }
};

extern "C" void kernel_launch(void* const* d_in, const int* in_sizes, int n_in,
                              void* d_out, int out_size) {
    static HbsRes res;   // host-side objects only; created once

    const float* x      = (const float*)d_in[0];
    const float* W      = (const float*)d_in[1];
    const float* a      = (const float*)d_in[2];
    const float* n_vals = (const float*)d_in[3];
    const int*   n_src  = (const int*)d_in[4];
    const int*   n_dst  = (const int*)d_in[5];
    float* out = (float*)d_out;

    // fork: CSR build on s2 (independent of GEMM)
    cudaEventRecord(res.evFork, 0);
    cudaStreamWaitEvent(res.s2, res.evFork, 0);

    zero_kernel<<<(N_CELLS + 255) / 256, 256, 0, res.s2>>>();
    hist_kernel<<<(N_EDGES + 255) / 256, 256, 0, res.s2>>>(n_src);
    alloc_kernel<<<(N_CELLS + 255) / 256, 256, 0, res.s2>>>();
    scatter_kernel<<<(N_EDGES + 255) / 256, 256, 0, res.s2>>>(n_src, n_dst, n_vals);
    cudaEventRecord(res.evJoin, res.s2);

    // main stream: GEMM then scores
    const int gemm_blocks = (N_CELLS + BM - 1) / BM;            // 391
    gemm_kernel<<<gemm_blocks, 256>>>(x, W);

    const int warp_blocks = (N_CELLS * 32 + 255) / 256;         // 6250
    score_kernel<<<warp_blocks, 256>>>(a);

    // join, then aggregate
    cudaStreamWaitEvent(0, res.evJoin, 0);
    agg_kernel<<<warp_blocks, 256>>>(out);
}

// round 9
// speedup vs baseline: 1.2181x; 1.0868x over previous
#include <cuda_runtime.h>
#include <cuda_fp16.h>

#define N_CELLS 50000
#define N_EDGES 1600000
#define D_IN 256
#define D_OUT 128

// ---- scratch (device globals; no allocation allowed) ----
__device__ float  g_m[N_CELLS * D_OUT];     // x @ W fp32 (frozen numerics; feeds scores)
__device__ __half g_mh[N_CELLS * D_OUT];    // fp16 copy (feeds agg numerator)
__device__ float  g_ssrc[N_CELLS];
__device__ float  g_sdst[N_CELLS];
__device__ int    g_cnt[N_CELLS];
__device__ int    g_rowstart[N_CELLS];
__device__ int    g_fill[N_CELLS];
__device__ int    g_total;
__device__ int2   g_pairs[N_EDGES];         // (dst, float_bits(n_val)) grouped by src

// ---- packed f32x2 helpers (FFMA2: each half IEEE fp32 RN, bit == scalar fmaf) ----
__device__ __forceinline__ unsigned long long pk2(float lo, float hi) {
    unsigned long long r;
    asm("mov.b64 %0, {%1, %2};" : "=l"(r) : "f"(lo), "f"(hi));
    return r;
}
__device__ __forceinline__ void upk2(unsigned long long v, float& lo, float& hi) {
    asm("mov.b64 {%0, %1}, %2;" : "=f"(lo), "=f"(hi) : "l"(v));
}
__device__ __forceinline__ unsigned long long ffma2(unsigned long long a,
                                                    unsigned long long b,
                                                    unsigned long long c) {
    unsigned long long d;
    asm("fma.rn.f32x2 %0, %1, %2, %3;" : "=l"(d) : "l"(a), "l"(b), "l"(c));
    return d;
}

// ================= GEMM: g_m = x @ W (k-ascending fma chain per element, FFMA2 packed) =================
#define BM 128
#define BN 128
#define BK 16

__global__ __launch_bounds__(256) void gemm_kernel(const float* __restrict__ x,
                                                   const float* __restrict__ W) {
    __shared__ float As[BK][BM + 4];   // +4 keeps rows 16B-aligned and banks spread
    __shared__ float Bs[BK][BN];
    const int tid = threadIdx.x;
    const int blockRow = blockIdx.x * BM;
    const int tx = tid & 15;
    const int ty = tid >> 4;

    unsigned long long acc2[8][4];
#pragma unroll
    for (int r = 0; r < 8; r++)
#pragma unroll
        for (int c = 0; c < 4; c++) acc2[r][c] = 0ull;

    const int rowA = tid >> 2;
    const int colA = (tid & 3) << 2;
    const int rowB = tid >> 5;
    const int colB = (tid & 31) << 2;

    for (int kk = 0; kk < D_IN; kk += BK) {
#pragma unroll
        for (int h = 0; h < 2; h++) {
            int r = rowA + h * 64;
            int gr = blockRow + r;
            float4 v = make_float4(0.f, 0.f, 0.f, 0.f);
            if (gr < N_CELLS)
                v = *(const float4*)(x + (size_t)gr * D_IN + kk + colA);
            As[colA + 0][r] = v.x;
            As[colA + 1][r] = v.y;
            As[colA + 2][r] = v.z;
            As[colA + 3][r] = v.w;
        }
#pragma unroll
        for (int h = 0; h < 2; h++) {
            int r = rowB + h * 8;
            float4 v = *(const float4*)(W + (size_t)(kk + r) * D_OUT + colB);
            *(float4*)(&Bs[r][colB]) = v;
        }
        __syncthreads();
#pragma unroll
        for (int k = 0; k < BK; k++) {
            float4 a0 = *(const float4*)(&As[k][ty * 8]);
            float4 a1 = *(const float4*)(&As[k][ty * 8 + 4]);
            float4 b0 = *(const float4*)(&Bs[k][tx * 8]);
            float4 b1 = *(const float4*)(&Bs[k][tx * 8 + 4]);
            unsigned long long nn[4] = {pk2(b0.x, b0.y), pk2(b0.z, b0.w),
                                        pk2(b1.x, b1.y), pk2(b1.z, b1.w)};
            float mA[8] = {a0.x, a0.y, a0.z, a0.w, a1.x, a1.y, a1.z, a1.w};
#pragma unroll
            for (int r = 0; r < 8; r++) {
                unsigned long long md = pk2(mA[r], mA[r]);
#pragma unroll
                for (int c = 0; c < 4; c++)
                    acc2[r][c] = ffma2(md, nn[c], acc2[r][c]);
            }
        }
        __syncthreads();
    }
#pragma unroll
    for (int r = 0; r < 8; r++) {
        int gr = blockRow + ty * 8 + r;
        if (gr < N_CELLS) {
            float f[8];
            upk2(acc2[r][0], f[0], f[1]);
            upk2(acc2[r][1], f[2], f[3]);
            upk2(acc2[r][2], f[4], f[5]);
            upk2(acc2[r][3], f[6], f[7]);
            float* dst = g_m + (size_t)gr * D_OUT + tx * 8;
            *(float4*)dst = make_float4(f[0], f[1], f[2], f[3]);
            *(float4*)(dst + 4) = make_float4(f[4], f[5], f[6], f[7]);
            __half2 h0 = __floats2half2_rn(f[0], f[1]);
            __half2 h1 = __floats2half2_rn(f[2], f[3]);
            __half2 h2 = __floats2half2_rn(f[4], f[5]);
            __half2 h3 = __floats2half2_rn(f[6], f[7]);
            uint4 hv;
            hv.x = *(unsigned int*)&h0;
            hv.y = *(unsigned int*)&h1;
            hv.z = *(unsigned int*)&h2;
            hv.w = *(unsigned int*)&h3;
            *(uint4*)(g_mh + (size_t)gr * D_OUT + tx * 8) = hv;
        }
    }
}

// ================= scores: cublas-gemv emulation (FROZEN numerics) =================
__global__ __launch_bounds__(256) void score_kernel(const float* __restrict__ a) {
    __shared__ float sa[2 * D_OUT];
    for (int j = threadIdx.x; j < 2 * D_OUT; j += blockDim.x) sa[j] = a[j];
    __syncthreads();
    int row = (blockIdx.x * blockDim.x + threadIdx.x) >> 5;
    int l = threadIdx.x & 31;
    if (row >= N_CELLS) return;
    const float* __restrict__ mr = g_m + (size_t)row * D_OUT;

    float m0 = __ldg(mr + l);
    float m1 = __ldg(mr + l + 32);
    float m2 = __ldg(mr + l + 64);
    float m3 = __ldg(mr + l + 96);

    float ss = fmaf(m0, sa[l], 0.f);
    ss = fmaf(m1, sa[l + 32], ss);
    ss = fmaf(m2, sa[l + 64], ss);
    ss = fmaf(m3, sa[l + 96], ss);

    float sd = fmaf(m0, sa[D_OUT + l], 0.f);
    sd = fmaf(m1, sa[D_OUT + l + 32], sd);
    sd = fmaf(m2, sa[D_OUT + l + 64], sd);
    sd = fmaf(m3, sa[D_OUT + l + 96], sd);

#pragma unroll
    for (int off = 16; off > 0; off >>= 1) {
        ss += __shfl_down_sync(0xffffffffu, ss, off);
        sd += __shfl_down_sync(0xffffffffu, sd, off);
    }
    if (l == 0) {
        g_ssrc[row] = ss;
        g_sdst[row] = sd;
    }
}

// ================= CSR build (scan-free, 4 edges/thread) =================
__global__ void zero_kernel() {
    int i = blockIdx.x * blockDim.x + threadIdx.x;
    if (i < N_CELLS) g_cnt[i] = 0;
    if (i == 0) g_total = 0;
}

__global__ void hist_kernel(const int* __restrict__ n_src) {
    int e = (blockIdx.x * blockDim.x + threadIdx.x) * 4;
    if (e < N_EDGES) {
        int4 s = *(const int4*)(n_src + e);
        atomicAdd(&g_cnt[s.x], 1);
        atomicAdd(&g_cnt[s.y], 1);
        atomicAdd(&g_cnt[s.z], 1);
        atomicAdd(&g_cnt[s.w], 1);
    }
}

__global__ __launch_bounds__(256) void alloc_kernel() {
    int i = blockIdx.x * blockDim.x + threadIdx.x;
    int lane = threadIdx.x & 31;
    int cnt = (i < N_CELLS) ? g_cnt[i] : 0;
    int xv = cnt;
#pragma unroll
    for (int off = 1; off < 32; off <<= 1) {
        int y = __shfl_up_sync(0xffffffffu, xv, off);
        if (lane >= off) xv += y;
    }
    int excl = xv - cnt;
    int wtotal = __shfl_sync(0xffffffffu, xv, 31);
    int base = 0;
    if (lane == 0) base = atomicAdd(&g_total, wtotal);
    base = __shfl_sync(0xffffffffu, base, 0);
    if (i < N_CELLS) {
        int s = base + excl;
        g_rowstart[i] = s;
        g_fill[i] = s;
    }
}

__global__ void scatter_kernel(const int* __restrict__ n_src,
                               const int* __restrict__ n_dst,
                               const float* __restrict__ n_vals) {
    int e = (blockIdx.x * blockDim.x + threadIdx.x) * 4;
    if (e < N_EDGES) {
        int4 s = *(const int4*)(n_src + e);
        int4 d = *(const int4*)(n_dst + e);
        float4 v = *(const float4*)(n_vals + e);
        int p0 = atomicAdd(&g_fill[s.x], 1);
        int p1 = atomicAdd(&g_fill[s.y], 1);
        int p2 = atomicAdd(&g_fill[s.z], 1);
        int p3 = atomicAdd(&g_fill[s.w], 1);
        g_pairs[p0] = make_int2(d.x, __float_as_int(v.x));
        g_pairs[p1] = make_int2(d.y, __float_as_int(v.y));
        g_pairs[p2] = make_int2(d.z, __float_as_int(v.z));
        g_pairs[p3] = make_int2(d.w, __float_as_int(v.w));
    }
}

// ================= aggregation: one warp per cell (denominator FROZEN; numerator fp16 m) =================
__global__ __launch_bounds__(256) void agg_kernel(float* __restrict__ out) {
    int i = (blockIdx.x * blockDim.x + threadIdx.x) >> 5;
    int lane = threadIdx.x & 31;
    if (i >= N_CELLS) return;
    int start = g_rowstart[i];
    int d = g_cnt[i];
    int end = start + d;
    float si = g_ssrc[i];

    // pass 1: fp64 rs
    double rsd = 0.0;
    for (int j = start + lane; j < end; j += 32) {
        int dst = g_pairs[j].x;
        float z = si + g_sdst[dst];
        float e = z >= 0.f ? z : 0.2f * z;
        rsd += (double)e;
    }
#pragma unroll
    for (int off = 16; off > 0; off >>= 1)
        rsd += __shfl_xor_sync(0xffffffffu, rsd, off);
    float rsf = (float)rsd;

    // pass 2: numerator; lane owns 4 output cols; fp16 m gathers (8B/lane/edge)
    float4 acc = make_float4(0.f, 0.f, 0.f, 0.f);
    const uint2* __restrict__ MH = (const uint2*)g_mh;
#pragma unroll 2
    for (int j = start; j < end; j++) {
        int2 p = g_pairs[j];
        float z = si + g_sdst[p.x];
        float e = z >= 0.f ? z : 0.2f * z;
        float att = e / rsf;
        float tt = __int_as_float(p.y) * att;
        uint2 hv = __ldg(&MH[(size_t)p.x * 32 + lane]);
        __half2 h0 = *(__half2*)&hv.x;
        __half2 h1 = *(__half2*)&hv.y;
        float2 f0 = __half22float2(h0);
        float2 f1 = __half22float2(h1);
        acc.x = fmaf(tt, f0.x, acc.x);
        acc.y = fmaf(tt, f0.y, acc.y);
        acc.z = fmaf(tt, f1.x, acc.z);
        acc.w = fmaf(tt, f1.y, acc.w);
    }
    *((float4*)(out + (size_t)i * D_OUT) + lane) = acc;
}

// ================= launch (fork/join: CSR build overlaps GEMM) =================
struct HbsRes {
    cudaStream_t s2;
    cudaEvent_t evFork, evJoin;
    HbsRes() {
        cudaStreamCreateWithFlags(&s2, cudaStreamNonBlocking);
        cudaEventCreateWithFlags(&evFork, cudaEventDisableTiming);
        cudaEventCreateWithFlags(&evJoin, cudaEventDisableTiming);
    }
};

extern "C" void kernel_launch(void* const* d_in, const int* in_sizes, int n_in,
                              void* d_out, int out_size) {
    static HbsRes res;

    const float* x      = (const float*)d_in[0];
    const float* W      = (const float*)d_in[1];
    const float* a      = (const float*)d_in[2];
    const float* n_vals = (const float*)d_in[3];
    const int*   n_src  = (const int*)d_in[4];
    const int*   n_dst  = (const int*)d_in[5];
    float* out = (float*)d_out;

    cudaEventRecord(res.evFork, 0);
    cudaStreamWaitEvent(res.s2, res.evFork, 0);

    zero_kernel<<<(N_CELLS + 255) / 256, 256, 0, res.s2>>>();
    hist_kernel<<<(N_EDGES / 4 + 255) / 256, 256, 0, res.s2>>>(n_src);
    alloc_kernel<<<(N_CELLS + 255) / 256, 256, 0, res.s2>>>();
    scatter_kernel<<<(N_EDGES / 4 + 255) / 256, 256, 0, res.s2>>>(n_src, n_dst, n_vals);
    cudaEventRecord(res.evJoin, res.s2);

    const int gemm_blocks = (N_CELLS + BM - 1) / BM;            // 391
    gemm_kernel<<<gemm_blocks, 256>>>(x, W);

    const int warp_blocks = (N_CELLS * 32 + 255) / 256;         // 6250
    score_kernel<<<warp_blocks, 256>>>(a);

    cudaStreamWaitEvent(0, res.evJoin, 0);
    agg_kernel<<<warp_blocks, 256>>>(out);
}

// round 10
// speedup vs baseline: 1.2482x; 1.0247x over previous
#include <cuda_runtime.h>
#include <cuda_fp16.h>

#define N_CELLS 50000
#define N_EDGES 1600000
#define D_IN 256
#define D_OUT 128
#define MAXD 128

// ---- scratch (device globals; no allocation allowed) ----
__device__ float  g_m[N_CELLS * D_OUT];     // x @ W fp32 (frozen numerics; feeds scores)
__device__ __half g_mh[N_CELLS * D_OUT];    // fp16 copy (feeds agg numerator)
__device__ float  g_ssrc[N_CELLS];
__device__ float  g_sdst[N_CELLS];
__device__ int    g_cnt[N_CELLS];
__device__ int    g_rowstart[N_CELLS];
__device__ int    g_fill[N_CELLS];
__device__ int    g_total;
__device__ int2   g_pairs[N_EDGES];         // (dst, float_bits(n_val)) grouped by src

// ---- packed f32x2 helpers (FFMA2: each half IEEE fp32 RN, bit == scalar fmaf) ----
__device__ __forceinline__ unsigned long long pk2(float lo, float hi) {
    unsigned long long r;
    asm("mov.b64 %0, {%1, %2};" : "=l"(r) : "f"(lo), "f"(hi));
    return r;
}
__device__ __forceinline__ void upk2(unsigned long long v, float& lo, float& hi) {
    asm("mov.b64 {%0, %1}, %2;" : "=f"(lo), "=f"(hi) : "l"(v));
}
__device__ __forceinline__ unsigned long long ffma2(unsigned long long a,
                                                    unsigned long long b,
                                                    unsigned long long c) {
    unsigned long long d;
    asm("fma.rn.f32x2 %0, %1, %2, %3;" : "=l"(d) : "l"(a), "l"(b), "l"(c));
    return d;
}

// ================= GEMM: g_m = x @ W (software-pipelined, FFMA2, frozen k-order) =================
#define BM 128
#define BN 128
#define BK 16

__global__ __launch_bounds__(256) void gemm_kernel(const float* __restrict__ x,
                                                   const float* __restrict__ W) {
    __shared__ float As[BK][BM + 4];
    __shared__ float Bs[BK][BN];
    const int tid = threadIdx.x;
    const int blockRow = blockIdx.x * BM;
    const int tx = tid & 15;
    const int ty = tid >> 4;

    unsigned long long acc2[8][4];
#pragma unroll
    for (int r = 0; r < 8; r++)
#pragma unroll
        for (int c = 0; c < 4; c++) acc2[r][c] = 0ull;

    const int rowA = tid >> 2;          // 0..63
    const int colA = (tid & 3) << 2;    // 0,4,8,12
    const int rowB = tid >> 5;          // 0..7
    const int colB = (tid & 31) << 2;   // 0..124

    const int grA0 = blockRow + rowA;
    const int grA1 = blockRow + rowA + 64;
    const bool okA0 = grA0 < N_CELLS;
    const bool okA1 = grA1 < N_CELLS;
    const float* pA0 = x + (size_t)(okA0 ? grA0 : 0) * D_IN + colA;
    const float* pA1 = x + (size_t)(okA1 ? grA1 : 0) * D_IN + colA;
    const float* pB0 = W + (size_t)rowB * D_OUT + colB;
    const float* pB1 = W + (size_t)(rowB + 8) * D_OUT + colB;

    // prologue: tile kk=0 into smem
    {
        float4 a0 = okA0 ? *(const float4*)pA0 : make_float4(0.f, 0.f, 0.f, 0.f);
        float4 a1 = okA1 ? *(const float4*)pA1 : make_float4(0.f, 0.f, 0.f, 0.f);
        float4 b0 = *(const float4*)pB0;
        float4 b1 = *(const float4*)pB1;
        As[colA + 0][rowA] = a0.x; As[colA + 1][rowA] = a0.y;
        As[colA + 2][rowA] = a0.z; As[colA + 3][rowA] = a0.w;
        As[colA + 0][rowA + 64] = a1.x; As[colA + 1][rowA + 64] = a1.y;
        As[colA + 2][rowA + 64] = a1.z; As[colA + 3][rowA + 64] = a1.w;
        *(float4*)(&Bs[rowB][colB]) = b0;
        *(float4*)(&Bs[rowB + 8][colB]) = b1;
    }
    __syncthreads();

    for (int kk = 0; kk < D_IN; kk += BK) {
        // prefetch next tile into registers
        float4 na0, na1, nb0, nb1;
        const bool more = (kk + BK) < D_IN;
        if (more) {
            na0 = okA0 ? *(const float4*)(pA0 + kk + BK) : make_float4(0.f, 0.f, 0.f, 0.f);
            na1 = okA1 ? *(const float4*)(pA1 + kk + BK) : make_float4(0.f, 0.f, 0.f, 0.f);
            nb0 = *(const float4*)(pB0 + (size_t)(kk + BK) * D_OUT);
            nb1 = *(const float4*)(pB1 + (size_t)(kk + BK) * D_OUT);
        }
#pragma unroll
        for (int k = 0; k < BK; k++) {
            float4 a0 = *(const float4*)(&As[k][ty * 8]);
            float4 a1 = *(const float4*)(&As[k][ty * 8 + 4]);
            float4 b0 = *(const float4*)(&Bs[k][tx * 8]);
            float4 b1 = *(const float4*)(&Bs[k][tx * 8 + 4]);
            unsigned long long nn[4] = {pk2(b0.x, b0.y), pk2(b0.z, b0.w),
                                        pk2(b1.x, b1.y), pk2(b1.z, b1.w)};
            float mA[8] = {a0.x, a0.y, a0.z, a0.w, a1.x, a1.y, a1.z, a1.w};
#pragma unroll
            for (int r = 0; r < 8; r++) {
                unsigned long long md = pk2(mA[r], mA[r]);
#pragma unroll
                for (int c = 0; c < 4; c++)
                    acc2[r][c] = ffma2(md, nn[c], acc2[r][c]);
            }
        }
        __syncthreads();
        if (more) {
            As[colA + 0][rowA] = na0.x; As[colA + 1][rowA] = na0.y;
            As[colA + 2][rowA] = na0.z; As[colA + 3][rowA] = na0.w;
            As[colA + 0][rowA + 64] = na1.x; As[colA + 1][rowA + 64] = na1.y;
            As[colA + 2][rowA + 64] = na1.z; As[colA + 3][rowA + 64] = na1.w;
            *(float4*)(&Bs[rowB][colB]) = nb0;
            *(float4*)(&Bs[rowB + 8][colB]) = nb1;
            __syncthreads();
        }
    }

#pragma unroll
    for (int r = 0; r < 8; r++) {
        int gr = blockRow + ty * 8 + r;
        if (gr < N_CELLS) {
            float f[8];
            upk2(acc2[r][0], f[0], f[1]);
            upk2(acc2[r][1], f[2], f[3]);
            upk2(acc2[r][2], f[4], f[5]);
            upk2(acc2[r][3], f[6], f[7]);
            float* dst = g_m + (size_t)gr * D_OUT + tx * 8;
            *(float4*)dst = make_float4(f[0], f[1], f[2], f[3]);
            *(float4*)(dst + 4) = make_float4(f[4], f[5], f[6], f[7]);
            __half2 h0 = __floats2half2_rn(f[0], f[1]);
            __half2 h1 = __floats2half2_rn(f[2], f[3]);
            __half2 h2 = __floats2half2_rn(f[4], f[5]);
            __half2 h3 = __floats2half2_rn(f[6], f[7]);
            uint4 hv;
            hv.x = *(unsigned int*)&h0;
            hv.y = *(unsigned int*)&h1;
            hv.z = *(unsigned int*)&h2;
            hv.w = *(unsigned int*)&h3;
            *(uint4*)(g_mh + (size_t)gr * D_OUT + tx * 8) = hv;
        }
    }
}

// ================= scores: cublas-gemv emulation (FROZEN numerics) =================
__global__ __launch_bounds__(256) void score_kernel(const float* __restrict__ a) {
    __shared__ float sa[2 * D_OUT];
    for (int j = threadIdx.x; j < 2 * D_OUT; j += blockDim.x) sa[j] = a[j];
    __syncthreads();
    int row = (blockIdx.x * blockDim.x + threadIdx.x) >> 5;
    int l = threadIdx.x & 31;
    if (row >= N_CELLS) return;
    const float* __restrict__ mr = g_m + (size_t)row * D_OUT;

    float m0 = __ldg(mr + l);
    float m1 = __ldg(mr + l + 32);
    float m2 = __ldg(mr + l + 64);
    float m3 = __ldg(mr + l + 96);

    float ss = fmaf(m0, sa[l], 0.f);
    ss = fmaf(m1, sa[l + 32], ss);
    ss = fmaf(m2, sa[l + 64], ss);
    ss = fmaf(m3, sa[l + 96], ss);

    float sd = fmaf(m0, sa[D_OUT + l], 0.f);
    sd = fmaf(m1, sa[D_OUT + l + 32], sd);
    sd = fmaf(m2, sa[D_OUT + l + 64], sd);
    sd = fmaf(m3, sa[D_OUT + l + 96], sd);

#pragma unroll
    for (int off = 16; off > 0; off >>= 1) {
        ss += __shfl_down_sync(0xffffffffu, ss, off);
        sd += __shfl_down_sync(0xffffffffu, sd, off);
    }
    if (l == 0) {
        g_ssrc[row] = ss;
        g_sdst[row] = sd;
    }
}

// ================= CSR build (scan-free, 4 edges/thread) =================
__global__ void zero_kernel() {
    int i = blockIdx.x * blockDim.x + threadIdx.x;
    if (i < N_CELLS) g_cnt[i] = 0;
    if (i == 0) g_total = 0;
}

__global__ void hist_kernel(const int* __restrict__ n_src) {
    int e = (blockIdx.x * blockDim.x + threadIdx.x) * 4;
    if (e < N_EDGES) {
        int4 s = *(const int4*)(n_src + e);
        atomicAdd(&g_cnt[s.x], 1);
        atomicAdd(&g_cnt[s.y], 1);
        atomicAdd(&g_cnt[s.z], 1);
        atomicAdd(&g_cnt[s.w], 1);
    }
}

__global__ __launch_bounds__(256) void alloc_kernel() {
    int i = blockIdx.x * blockDim.x + threadIdx.x;
    int lane = threadIdx.x & 31;
    int cnt = (i < N_CELLS) ? g_cnt[i] : 0;
    int xv = cnt;
#pragma unroll
    for (int off = 1; off < 32; off <<= 1) {
        int y = __shfl_up_sync(0xffffffffu, xv, off);
        if (lane >= off) xv += y;
    }
    int excl = xv - cnt;
    int wtotal = __shfl_sync(0xffffffffu, xv, 31);
    int base = 0;
    if (lane == 0) base = atomicAdd(&g_total, wtotal);
    base = __shfl_sync(0xffffffffu, base, 0);
    if (i < N_CELLS) {
        int s = base + excl;
        g_rowstart[i] = s;
        g_fill[i] = s;
    }
}

__global__ void scatter_kernel(const int* __restrict__ n_src,
                               const int* __restrict__ n_dst,
                               const float* __restrict__ n_vals) {
    int e = (blockIdx.x * blockDim.x + threadIdx.x) * 4;
    if (e < N_EDGES) {
        int4 s = *(const int4*)(n_src + e);
        int4 d = *(const int4*)(n_dst + e);
        float4 v = *(const float4*)(n_vals + e);
        int p0 = atomicAdd(&g_fill[s.x], 1);
        int p1 = atomicAdd(&g_fill[s.y], 1);
        int p2 = atomicAdd(&g_fill[s.z], 1);
        int p3 = atomicAdd(&g_fill[s.w], 1);
        g_pairs[p0] = make_int2(d.x, __float_as_int(v.x));
        g_pairs[p1] = make_int2(d.y, __float_as_int(v.y));
        g_pairs[p2] = make_int2(d.z, __float_as_int(v.z));
        g_pairs[p3] = make_int2(d.w, __float_as_int(v.w));
    }
}

// ================= aggregation: one warp per cell (denominator FROZEN; numerator fp16 m) =================
__global__ __launch_bounds__(256) void agg_kernel(float* __restrict__ out) {
    __shared__ float ebuf[8][MAXD];
    const int w = threadIdx.x >> 5;
    int i = (blockIdx.x * blockDim.x + threadIdx.x) >> 5;
    int lane = threadIdx.x & 31;
    if (i >= N_CELLS) return;
    int start = g_rowstart[i];
    int d = g_cnt[i];
    int end = start + d;
    float si = g_ssrc[i];

    // pass 1: e values (cached in smem) + fp64 rs
    double rsd = 0.0;
    for (int j = start + lane; j < end; j += 32) {
        int dst = g_pairs[j].x;
        float z = si + g_sdst[dst];
        float e = z >= 0.f ? z : 0.2f * z;
        int t = j - start;
        if (t < MAXD) ebuf[w][t] = e;
        rsd += (double)e;
    }
#pragma unroll
    for (int off = 16; off > 0; off >>= 1)
        rsd += __shfl_xor_sync(0xffffffffu, rsd, off);
    float rsf = (float)rsd;
    __syncwarp();

    // pass 2: numerator; lane owns 4 output cols; fp16 m gathers (8B/lane/edge)
    float4 acc = make_float4(0.f, 0.f, 0.f, 0.f);
    const uint2* __restrict__ MH = (const uint2*)g_mh;
#pragma unroll 2
    for (int t = 0; t < d; t++) {
        int2 p = g_pairs[start + t];
        float e;
        if (t < MAXD) {
            e = ebuf[w][t];
        } else {
            float z = si + g_sdst[p.x];
            e = z >= 0.f ? z : 0.2f * z;
        }
        float att = e / rsf;
        float tt = __int_as_float(p.y) * att;
        uint2 hv = __ldg(&MH[(size_t)p.x * 32 + lane]);
        __half2 h0 = *(__half2*)&hv.x;
        __half2 h1 = *(__half2*)&hv.y;
        float2 f0 = __half22float2(h0);
        float2 f1 = __half22float2(h1);
        acc.x = fmaf(tt, f0.x, acc.x);
        acc.y = fmaf(tt, f0.y, acc.y);
        acc.z = fmaf(tt, f1.x, acc.z);
        acc.w = fmaf(tt, f1.y, acc.w);
    }
    *((float4*)(out + (size_t)i * D_OUT) + lane) = acc;
}

// ================= launch (fork/join: CSR build overlaps GEMM) =================
struct HbsRes {
    cudaStream_t s2;
    cudaEvent_t evFork, evJoin;
    HbsRes() {
        cudaStreamCreateWithFlags(&s2, cudaStreamNonBlocking);
        cudaEventCreateWithFlags(&evFork, cudaEventDisableTiming);
        cudaEventCreateWithFlags(&evJoin, cudaEventDisableTiming);
    }
};

extern "C" void kernel_launch(void* const* d_in, const int* in_sizes, int n_in,
                              void* d_out, int out_size) {
    static HbsRes res;

    const float* x      = (const float*)d_in[0];
    const float* W      = (const float*)d_in[1];
    const float* a      = (const float*)d_in[2];
    const float* n_vals = (const float*)d_in[3];
    const int*   n_src  = (const int*)d_in[4];
    const int*   n_dst  = (const int*)d_in[5];
    float* out = (float*)d_out;

    cudaEventRecord(res.evFork, 0);
    cudaStreamWaitEvent(res.s2, res.evFork, 0);

    zero_kernel<<<(N_CELLS + 255) / 256, 256, 0, res.s2>>>();
    hist_kernel<<<(N_EDGES / 4 + 255) / 256, 256, 0, res.s2>>>(n_src);
    alloc_kernel<<<(N_CELLS + 255) / 256, 256, 0, res.s2>>>();
    scatter_kernel<<<(N_EDGES / 4 + 255) / 256, 256, 0, res.s2>>>(n_src, n_dst, n_vals);
    cudaEventRecord(res.evJoin, res.s2);

    const int gemm_blocks = (N_CELLS + BM - 1) / BM;            // 391
    gemm_kernel<<<gemm_blocks, 256>>>(x, W);

    const int warp_blocks = (N_CELLS * 32 + 255) / 256;         // 6250
    score_kernel<<<warp_blocks, 256>>>(a);

    cudaStreamWaitEvent(0, res.evJoin, 0);
    agg_kernel<<<warp_blocks, 256>>>(out);
}